// round 11
// baseline (speedup 1.0000x reference)
#include <cuda_runtime.h>
#include <cuda_fp16.h>
#include <cstdint>

#define EMB_DIM 300
#define KP      304                 // K padded to multiple of 16
#define NTOT    2048
#define MTOT    32768
#define MTILE   128
#define NGRP    512                 // N-cols per CTA
#define NCHUNK  128
#define NCH_CTA (NGRP / NCHUNK)     // 4 chunks per CTA
#define KSTEPS  19
#define ASTR    312                 // halves per A row (conflict-free ldmatrix)
#define BSTR    136                 // halves per B row (conflict-free ldmatrix)
#define A_BYTES (MTILE * ASTR * 2)  // 79872
#define B_BYTES (KP * BSTR * 2)     // 82688 per chunk buffer
#define SMEM_BYTES (A_BYTES + 2 * B_BYTES)  // 245248? NO -- see below
#define SCALE 45.254833995939045f   // sqrt(2048)

// NOTE: B_BYTES = 304*136*2 = 82688; A + 2B = 245248 > 227KB. Use K-split
// buffers like R8? No — keep ONE chunk in flight per buffer but shrink BSTR
// is impossible. Instead: B buffer holds full chunk; use 2 buffers of the
// half-K layout? Simplest correct fit: BSTR stays, but buffers hold full
// KP rows => must reduce A or B. We drop ASTR padding is needed for ldmatrix.
// Resolution: split each chunk buffer in K as in R8 is extra barriers.
// Better: NCHUNK=96 -> B_BYTES=304*104*2=63232; A+2B=206336 fits. But 2048/96
// not integer. NCHUNK=64 -> BSTR=72, B_BYTES=43776, A+2B=167424 fits (R3 cfg).
// Use NCHUNK=64, NCH_CTA=8.
#undef NCHUNK
#undef NCH_CTA
#undef BSTR
#undef B_BYTES
#undef SMEM_BYTES
#define NCHUNK  64
#define NCH_CTA (NGRP / NCHUNK)     // 8 chunks per CTA
#define BSTR    72                  // halves per B row (conflict-free ldmatrix)
#define B_BYTES (KP * BSTR * 2)     // 43776
#define SMEM_BYTES (A_BYTES + 2 * B_BYTES)  // 167424 fits

__device__ __half g_Wh[KP * NTOT];  // fp16 W, K zero-padded (L2-resident)
__device__ float  g_bs[NTOT];       // bias * scale

__global__ void prep(const float* __restrict__ W, const float* __restrict__ b) {
    int i = blockIdx.x * blockDim.x + threadIdx.x;
    if (i < KP * NTOT) {
        int k = i / NTOT, n = i % NTOT;
        g_Wh[i] = __float2half_rn((k < EMB_DIM) ? W[k * NTOT + n] : 0.0f);
    }
    if (i < NTOT) g_bs[i] = b[i] * SCALE;
}

__device__ __forceinline__ void ldm_x4(uint32_t* r, uint32_t a) {
    asm volatile("ldmatrix.sync.aligned.m8n8.x4.shared.b16 {%0,%1,%2,%3}, [%4];"
                 : "=r"(r[0]), "=r"(r[1]), "=r"(r[2]), "=r"(r[3]) : "r"(a));
}
__device__ __forceinline__ void ldm_x4_t(uint32_t* r, uint32_t a) {
    asm volatile("ldmatrix.sync.aligned.m8n8.x4.trans.shared.b16 {%0,%1,%2,%3}, [%4];"
                 : "=r"(r[0]), "=r"(r[1]), "=r"(r[2]), "=r"(r[3]) : "r"(a));
}
__device__ __forceinline__ void mma16816(float* d, const uint32_t* a, const uint32_t* b) {
    asm volatile("mma.sync.aligned.m16n8k16.row.col.f32.f16.f16.f32 "
                 "{%0,%1,%2,%3}, {%4,%5,%6,%7}, {%8,%9}, {%0,%1,%2,%3};"
                 : "+f"(d[0]), "+f"(d[1]), "+f"(d[2]), "+f"(d[3])
                 : "r"(a[0]), "r"(a[1]), "r"(a[2]), "r"(a[3]),
                   "r"(b[0]), "r"(b[1]));
}

// cp.async one full B chunk: KP k-rows x 64 cols starting at n0 (2432 uint4)
__device__ __forceinline__ void cp_b(uint32_t dstU, int n0, int tid) {
    #pragma unroll
    for (int it = 0; it < 10; ++it) {
        int i = tid + it * 256;
        if (i < KP * 8) {
            int k = i >> 3, j = i & 7;
            uint32_t dst = dstU + (uint32_t)k * (BSTR * 2) + (uint32_t)j * 16;
            size_t g = __cvta_generic_to_global(g_Wh + (size_t)k * NTOT + n0 + 8 * j);
            asm volatile("cp.async.cg.shared.global [%0], [%1], 16;"
                         :: "r"(dst), "l"(g));
        }
    }
}

__global__ __launch_bounds__(256, 1)
void gemm_kernel(const int* __restrict__ x, const float* __restrict__ emb,
                 float* __restrict__ out) {
    extern __shared__ __half sm[];
    __half* A_s = sm;                          // [MTILE][ASTR]
    const uint32_t smem_u = (uint32_t)__cvta_generic_to_shared(sm);
    const uint32_t bBuf0 = smem_u + A_BYTES;
    const uint32_t bBuf1 = bBuf0 + B_BYTES;

    const int tid  = threadIdx.x;
    const int bid  = blockIdx.x;               // 1024 CTAs, 1-D grid
    const int m0   = (bid >> 2) * MTILE;       // adjacent CTAs share A tile
    const int nbas = (bid & 3) * NGRP;

    // prologue: chunks 0,1 in flight; A gather overlaps their latency
    cp_b(bBuf0, nbas, tid);
    asm volatile("cp.async.commit_group;" ::: "memory");
    cp_b(bBuf1, nbas + NCHUNK, tid);
    asm volatile("cp.async.commit_group;" ::: "memory");

    // ---- Gather A: 128 rows, 2 threads/row, fp32 -> fp16 ----
    {
        int r = tid >> 1;
        int token = x[m0 + r];
        const float4* src = (const float4*)(emb + (size_t)token * EMB_DIM);
        __half* dstrow = A_s + r * ASTR;
        #pragma unroll
        for (int j = (tid & 1); j < 75; j += 2) {   // 75 float4 per row
            float4 v = src[j];
            __half2* d2 = (__half2*)(dstrow + 4 * j);
            d2[0] = __floats2half2_rn(v.x, v.y);
            d2[1] = __floats2half2_rn(v.z, v.w);
        }
        if (tid < MTILE) {                      // zero K pad 300..303
            __half2* zp = (__half2*)(A_s + tid * ASTR + 300);
            zp[0] = __half2half2(__float2half(0.0f));
            zp[1] = __half2half2(__float2half(0.0f));
        }
    }

    const int lane = tid & 31, wid = tid >> 5;   // 8 warps
    const int wm = wid & 1;         // 0..1 : m64 each
    const int wn = wid >> 1;        // 0..3 : n32... (n64-chunk is 64 wide; 4 n-warps
                                    //  of n16? No: NCHUNK=64 -> warp n = 16?)
    // With NCHUNK=64 and 8 warps we use 2m x 4n of m64 x n16? Too thin.
    // Instead: 4m x 2n of m32 x n32 (R4 warp shape, proven conflict-free).
    const int wm2 = wid & 3;        // 0..3 : m32 each
    const int wn2 = wid >> 2;       // 0..1 : n32 each
    const int bq = lane >> 3, rq = lane & 7;

    const uint32_t aBase = smem_u
        + (uint32_t)((wm2 * 32 + (bq & 1) * 8 + rq) * ASTR) * 2
        + (uint32_t)(bq >> 1) * 16;
    const uint32_t bLane = (uint32_t)(((bq & 1) * 8 + rq) * BSTR) * 2
                         + (uint32_t)(wn2 * 64 + (bq >> 1) * 16);
    (void)wm; (void)wn;

    #pragma unroll 1
    for (int nc = 0; nc < NCH_CTA; ++nc) {
        asm volatile("cp.async.wait_group 1;" ::: "memory");
        __syncthreads();

        float acc[2][4][4];
        #pragma unroll
        for (int mt = 0; mt < 2; ++mt)
            #pragma unroll
            for (int nt = 0; nt < 4; ++nt)
                #pragma unroll
                for (int q = 0; q < 4; ++q) acc[mt][nt][q] = 0.0f;

        // ---- 19-kstep MMA burst, frag double-buffered, m32 x n32 ----
        const uint32_t bBase = ((nc & 1) ? bBuf1 : bBuf0) + bLane;
        uint32_t af[2][2][4], bf[2][2][4];
        #pragma unroll
        for (int mt = 0; mt < 2; ++mt)
            ldm_x4(af[0][mt], aBase + (uint32_t)(mt * 16 * ASTR) * 2);
        #pragma unroll
        for (int p = 0; p < 2; ++p)
            ldm_x4_t(bf[0][p], bBase + (uint32_t)p * 32);

        #pragma unroll
        for (int ks = 0; ks < KSTEPS; ++ks) {
            int cur = ks & 1, nxt = cur ^ 1;
            if (ks + 1 < KSTEPS) {
                uint32_t kbA = (uint32_t)(ks + 1) * 32;
                uint32_t kbB = (uint32_t)(ks + 1) * 16 * (BSTR * 2);
                #pragma unroll
                for (int mt = 0; mt < 2; ++mt)
                    ldm_x4(af[nxt][mt],
                           aBase + (uint32_t)(mt * 16 * ASTR) * 2 + kbA);
                #pragma unroll
                for (int p = 0; p < 2; ++p)
                    ldm_x4_t(bf[nxt][p], bBase + (uint32_t)p * 32 + kbB);
            }
            #pragma unroll
            for (int mt = 0; mt < 2; ++mt)
                #pragma unroll
                for (int nt = 0; nt < 4; ++nt) {
                    uint32_t bb[2] = { bf[cur][nt >> 1][(nt & 1) * 2],
                                       bf[cur][nt >> 1][(nt & 1) * 2 + 1] };
                    mma16816(acc[mt][nt], af[cur][mt], bb);
                }
        }
        __syncthreads();                 // all warps done reading this buffer

        if (nc + 2 < NCH_CTA)
            cp_b((nc & 1) ? bBuf1 : bBuf0, nbas + (nc + 2) * NCHUNK, tid);
        asm volatile("cp.async.commit_group;" ::: "memory");

        // ---- epilogue (overlaps the cp.async just issued) ----
        int n0 = nbas + nc * NCHUNK;
        #pragma unroll
        for (int nt = 0; nt < 4; ++nt) {
            int col = n0 + wn2 * 32 + nt * 8 + (lane & 3) * 2;
            float2 cb = *(const float2*)(g_bs + col);
            #pragma unroll
            for (int mt = 0; mt < 2; ++mt) {
                int row = m0 + wm2 * 32 + mt * 16 + (lane >> 2);
                float2 v0 = { fmaf(acc[mt][nt][0], SCALE, cb.x),
                              fmaf(acc[mt][nt][1], SCALE, cb.y) };
                float2 v1 = { fmaf(acc[mt][nt][2], SCALE, cb.x),
                              fmaf(acc[mt][nt][3], SCALE, cb.y) };
                *(float2*)(out + (size_t)row * NTOT + col)       = v0;
                *(float2*)(out + (size_t)(row + 8) * NTOT + col) = v1;
            }
        }
    }
}

extern "C" void kernel_launch(void* const* d_in, const int* in_sizes, int n_in,
                              void* d_out, int out_size) {
    const int*   x    = (const int*)  d_in[0];
    const float* emb  = (const float*)d_in[1];
    const float* W    = (const float*)d_in[2];
    const float* bias = (const float*)d_in[3];
    float*       out  = (float*)      d_out;

    cudaFuncSetAttribute(gemm_kernel, cudaFuncAttributeMaxDynamicSharedMemorySize,
                         SMEM_BYTES);

    prep<<<(KP * NTOT + 255) / 256, 256>>>(W, bias);
    gemm_kernel<<<(MTOT / MTILE) * (NTOT / NGRP), 256, SMEM_BYTES>>>(x, emb, out);
}

// round 12
// speedup vs baseline: 1.2883x; 1.2883x over previous
#include <cuda_runtime.h>
#include <cuda_fp16.h>
#include <cstdint>

#define EMB_DIM 300
#define KP      304
#define NTOT    2048
#define MTOT    32768
#define MTILE   128
#define NCHUNK  256
#define NCHUNKS (NTOT / NCHUNK)      // 8
#define A_ROWB  608                  // 304 halves, unpadded, swizzled
#define B_ROWB  128                  // 64 halves per slice row, swizzled
#define B_SLICE (300 * B_ROWB)       // 38400 (rows 300-303 never loaded)
#define B_TOT   (4 * B_SLICE)        // 153600
#define A_BYTES (MTILE * A_ROWB)     // 77824
#define SMEM_BYTES (B_TOT + A_BYTES) // 231424 <= 232448
#define SCALE 45.254833995939045f

__device__ __half g_Wh[KP * NTOT];   // fp16 W, K zero-padded rows
__device__ float  g_bs[NTOT];        // bias * scale

__global__ void prep(const float* __restrict__ W, const float* __restrict__ b) {
    int i = blockIdx.x * blockDim.x + threadIdx.x;
    if (i < KP * NTOT) {
        int k = i / NTOT, n = i % NTOT;
        g_Wh[i] = __float2half_rn((k < EMB_DIM) ? W[k * NTOT + n] : 0.0f);
    }
    if (i < NTOT) g_bs[i] = b[i] * SCALE;
}

__device__ __forceinline__ void ldm_x4(uint32_t* r, uint32_t a) {
    asm volatile("ldmatrix.sync.aligned.m8n8.x4.shared.b16 {%0,%1,%2,%3}, [%4];"
                 : "=r"(r[0]), "=r"(r[1]), "=r"(r[2]), "=r"(r[3]) : "r"(a));
}
__device__ __forceinline__ void ldm_x4_t(uint32_t* r, uint32_t a) {
    asm volatile("ldmatrix.sync.aligned.m8n8.x4.trans.shared.b16 {%0,%1,%2,%3}, [%4];"
                 : "=r"(r[0]), "=r"(r[1]), "=r"(r[2]), "=r"(r[3]) : "r"(a));
}
__device__ __forceinline__ void mma16816(float* d, const uint32_t* a, const uint32_t* b) {
    asm volatile("mma.sync.aligned.m16n8k16.row.col.f32.f16.f16.f32 "
                 "{%0,%1,%2,%3}, {%4,%5,%6,%7}, {%8,%9}, {%0,%1,%2,%3};"
                 : "+f"(d[0]), "+f"(d[1]), "+f"(d[2]), "+f"(d[3])
                 : "r"(a[0]), "r"(a[1]), "r"(a[2]), "r"(a[3]),
                   "r"(b[0]), "r"(b[1]));
}

// cp.async k-rows [g*64, +64|44) x n-cols [n0, n0+64) into pair slice.
// Pair-split: wm picks which half of the rows this warp issues.
__device__ __forceinline__ void issue_group(uint32_t bSliceU, int n0, int g,
                                            int wm, int lane) {
    int start = g * 64;
    int cnt   = (g < 4) ? 32 : 22;          // half of 64 / 44
    start += wm * cnt;
    int seg = lane & 7;
    int r0  = start + (lane >> 3);
    int iters = (cnt + 3) >> 2;             // 8 or 6
    for (int it = 0; it < iters; ++it) {
        int row = r0 + it * 4;
        if (row < start + cnt) {
            uint32_t dst = bSliceU + (uint32_t)row * B_ROWB
                         + (uint32_t)((seg ^ (row & 7)) * 16);
            size_t gsrc = __cvta_generic_to_global(
                g_Wh + (size_t)row * NTOT + n0 + seg * 8);
            asm volatile("cp.async.cg.shared.global [%0], [%1], 16;"
                         :: "r"(dst), "l"(gsrc));
        }
    }
}

__global__ __launch_bounds__(256, 1)
void gemm_kernel(const int* __restrict__ x, const float* __restrict__ emb,
                 float* __restrict__ out) {
    extern __shared__ char sm[];
    const uint32_t smem_u = (uint32_t)__cvta_generic_to_shared(sm);
    const uint32_t aU = smem_u + B_TOT;

    const int tid  = threadIdx.x;
    const int lane = tid & 31, wid = tid >> 5;       // 8 warps
    const int wm = wid & 1;                          // m64 half
    const int wn = wid >> 1;                         // 0..3 : n64 slice owner pair
    const int m0 = blockIdx.x * MTILE;
    const uint32_t bSliceU = smem_u + (uint32_t)wn * B_SLICE;

    // ---- prologue: issue chunk0 groups 0..3 for this pair (4 commits) ----
    #pragma unroll
    for (int g = 0; g < 4; ++g) {
        issue_group(bSliceU, wn * 64, g, wm, lane);
        asm volatile("cp.async.commit_group;" ::: "memory");
    }

    // ---- gather A (swizzled, unpadded rows): 128 rows, 2 threads/row ----
    {
        int r = tid >> 1;
        int token = x[m0 + r];
        const float4* src = (const float4*)(emb + (size_t)token * EMB_DIM);
        char* arow = sm + B_TOT + r * A_ROWB;
        int r7 = r & 7;
        #pragma unroll
        for (int j = (tid & 1); j < 75; j += 2) {    // 75 float4 per row
            float4 v = src[j];
            int c16 = j >> 1;
            int swc = (c16 < 32) ? (c16 ^ r7) : c16;
            char* dp = arow + swc * 16 + (j & 1) * 8;
            ((__half2*)dp)[0] = __floats2half2_rn(v.x, v.y);
            ((__half2*)dp)[1] = __floats2half2_rn(v.z, v.w);
        }
        if ((tid & 1) == 0) {                        // zero k 300..303 (seg 37, hi 8B)
            char* dp = arow + 37 * 16 + 8;
            ((__half2*)dp)[0] = __half2half2(__float2half(0.0f));
            ((__half2*)dp)[1] = __half2half2(__float2half(0.0f));
        }
    }
    __syncthreads();    // A visible to all; B is pair-self-synced from here on

    // ---- lane constants ----
    const int bq = lane >> 3, rq = lane & 7, cb = bq >> 1;
    uint32_t aRowByte[4];
    #pragma unroll
    for (int mt = 0; mt < 4; ++mt)
        aRowByte[mt] = aU + (uint32_t)((wm * 64 + mt * 16 + (bq & 1) * 8 + rq) * A_ROWB);
    const uint32_t bRowByte = bSliceU + (uint32_t)(((bq & 1) * 8 + rq) * B_ROWB);
    uint32_t boff[4];
    #pragma unroll
    for (int p = 0; p < 4; ++p)
        boff[p] = (uint32_t)(((p * 2 + cb) ^ rq) * 16);
    const int barId = wn + 1;

    float acc[4][8][4];
    #pragma unroll
    for (int mt = 0; mt < 4; ++mt)
        #pragma unroll
        for (int nt = 0; nt < 8; ++nt)
            #pragma unroll
            for (int q = 0; q < 4; ++q) acc[mt][nt][q] = 0.0f;

    int s = 0;
    #pragma unroll 1
    for (int c = 0; c < NCHUNKS; ++c) {
        #pragma unroll 1
        for (int g = 0; g < 5; ++g, ++s) {
            // step s data = commit #(s+1); uniform ledger: wait to <=3 pending
            asm volatile("cp.async.wait_group 3;" ::: "memory");
            asm volatile("bar.sync %0, 64;" :: "r"(barId) : "memory");

            int ks0 = g * 4;
            int ks1 = (g < 4) ? (ks0 + 4) : 19;
            for (int ks = ks0; ks < ks1; ++ks) {
                uint32_t cc = (uint32_t)(ks * 2 + cb);
                uint32_t aoff = ((cc < 32u) ? (cc ^ (uint32_t)rq) : cc) * 16u;
                uint32_t af[4][4], bf[4][4];
                #pragma unroll
                for (int mt = 0; mt < 4; ++mt)
                    ldm_x4(af[mt], aRowByte[mt] + aoff);
                uint32_t bks = bRowByte + (uint32_t)ks * (16 * B_ROWB);
                #pragma unroll
                for (int p = 0; p < 4; ++p)
                    ldm_x4_t(bf[p], bks + boff[p]);
                #pragma unroll
                for (int mt = 0; mt < 4; ++mt)
                    #pragma unroll
                    for (int nt = 0; nt < 8; ++nt) {
                        uint32_t bb[2] = { bf[nt >> 1][(nt & 1) * 2],
                                           bf[nt >> 1][(nt & 1) * 2 + 1] };
                        mma16816(acc[mt][nt], af[mt], bb);
                    }
            }

            // refill region consumed at step s-1 with its +5 successor (= step s+4)
            int s4 = s + 4;
            if (s4 < NCHUNKS * 5) {
                int c2 = s4 / 5, g2 = s4 - c2 * 5;
                issue_group(bSliceU, c2 * NCHUNK + wn * 64, g2, wm, lane);
            }
            asm volatile("cp.async.commit_group;" ::: "memory");
        }

        // ---- epilogue for chunk c (no barrier; overlaps other pairs) ----
        int n0 = c * NCHUNK;
        #pragma unroll
        for (int nt = 0; nt < 8; ++nt) {
            int col = n0 + wn * 64 + nt * 8 + (lane & 3) * 2;
            float2 cbia = *(const float2*)(g_bs + col);
            #pragma unroll
            for (int mt = 0; mt < 4; ++mt) {
                int row = m0 + wm * 64 + mt * 16 + (lane >> 2);
                float2 v0 = { fmaf(acc[mt][nt][0], SCALE, cbia.x),
                              fmaf(acc[mt][nt][1], SCALE, cbia.y) };
                float2 v1 = { fmaf(acc[mt][nt][2], SCALE, cbia.x),
                              fmaf(acc[mt][nt][3], SCALE, cbia.y) };
                *(float2*)(out + (size_t)row * NTOT + col)       = v0;
                *(float2*)(out + (size_t)(row + 8) * NTOT + col) = v1;
                acc[mt][nt][0] = 0.0f; acc[mt][nt][1] = 0.0f;
                acc[mt][nt][2] = 0.0f; acc[mt][nt][3] = 0.0f;
            }
        }
    }
}

extern "C" void kernel_launch(void* const* d_in, const int* in_sizes, int n_in,
                              void* d_out, int out_size) {
    const int*   x    = (const int*)  d_in[0];
    const float* emb  = (const float*)d_in[1];
    const float* W    = (const float*)d_in[2];
    const float* bias = (const float*)d_in[3];
    float*       out  = (float*)      d_out;

    cudaFuncSetAttribute(gemm_kernel, cudaFuncAttributeMaxDynamicSharedMemorySize,
                         SMEM_BYTES);

    prep<<<(KP * NTOT + 255) / 256, 256>>>(W, bias);
    gemm_kernel<<<MTOT / MTILE, 256, SMEM_BYTES>>>(x, emb, out);
}

// round 13
// speedup vs baseline: 1.3788x; 1.0703x over previous
#include <cuda_runtime.h>
#include <cuda_fp16.h>
#include <cstdint>

#define EMB_DIM 300
#define KP      304
#define NTOT    2048
#define MTOT    32768
#define MTILE   128
#define NCHUNK  256
#define NCHUNKS (NTOT / NCHUNK)      // 8
#define NGRP    3                    // K-groups per chunk (7/6/6 ksteps)
#define NSTEPS  (NCHUNKS * NGRP)     // 24 pipeline steps
#define A_ROWB  608                  // 304 halves, unpadded, swizzled
#define B_ROWB  128                  // 64 halves per slice row, swizzled
#define B_SLICE (300 * B_ROWB)       // 38400 (rows 300-303 never loaded)
#define B_TOT   (4 * B_SLICE)        // 153600
#define A_BYTES (MTILE * A_ROWB)     // 77824
#define SMEM_BYTES (B_TOT + A_BYTES) // 231424 <= 232448
#define SCALE 45.254833995939045f

__device__ __half g_Wh[KP * NTOT];   // fp16 W, K zero-padded rows
__device__ float  g_bs[NTOT];        // bias * scale

__global__ void prep(const float* __restrict__ W, const float* __restrict__ b) {
    int i = blockIdx.x * blockDim.x + threadIdx.x;
    if (i < KP * NTOT) {
        int k = i / NTOT, n = i % NTOT;
        g_Wh[i] = __float2half_rn((k < EMB_DIM) ? W[k * NTOT + n] : 0.0f);
    }
    if (i < NTOT) g_bs[i] = b[i] * SCALE;
}

__device__ __forceinline__ void ldm_x4(uint32_t* r, uint32_t a) {
    asm volatile("ldmatrix.sync.aligned.m8n8.x4.shared.b16 {%0,%1,%2,%3}, [%4];"
                 : "=r"(r[0]), "=r"(r[1]), "=r"(r[2]), "=r"(r[3]) : "r"(a));
}
__device__ __forceinline__ void ldm_x4_t(uint32_t* r, uint32_t a) {
    asm volatile("ldmatrix.sync.aligned.m8n8.x4.trans.shared.b16 {%0,%1,%2,%3}, [%4];"
                 : "=r"(r[0]), "=r"(r[1]), "=r"(r[2]), "=r"(r[3]) : "r"(a));
}
__device__ __forceinline__ void mma16816(float* d, const uint32_t* a, const uint32_t* b) {
    asm volatile("mma.sync.aligned.m16n8k16.row.col.f32.f16.f16.f32 "
                 "{%0,%1,%2,%3}, {%4,%5,%6,%7}, {%8,%9}, {%0,%1,%2,%3};"
                 : "+f"(d[0]), "+f"(d[1]), "+f"(d[2]), "+f"(d[3])
                 : "r"(a[0]), "r"(a[1]), "r"(a[2]), "r"(a[3]),
                   "r"(b[0]), "r"(b[1]));
}

// cp.async one K-group of the pair's n64 slice. Group row windows:
//   g0: [0,112)  g1: [112,208)  g2: [208,300)  (rows >=300 never loaded)
// wm splits each window between the two partner warps.
__device__ __forceinline__ void issue_group(uint32_t bSliceU, int n0, int g,
                                            int wm, int lane) {
    int start = (g == 0) ? 0 : (g == 1 ? 112 : 208);
    int cnt   = (g == 0) ? 56 : (g == 1 ? 48 : 46);   // per-warp rows
    start += wm * cnt;
    int seg = lane & 7;
    int r0  = start + (lane >> 3);
    int iters = (cnt + 3) >> 2;
    for (int it = 0; it < iters; ++it) {
        int row = r0 + it * 4;
        if (row < start + cnt) {
            uint32_t dst = bSliceU + (uint32_t)row * B_ROWB
                         + (uint32_t)((seg ^ (row & 7)) * 16);
            size_t gsrc = __cvta_generic_to_global(
                g_Wh + (size_t)row * NTOT + n0 + seg * 8);
            asm volatile("cp.async.cg.shared.global [%0], [%1], 16;"
                         :: "r"(dst), "l"(gsrc));
        }
    }
}

// fully-unrolled K-group compute: ksteps [KS0, KS0+KSN), warp tile m64 x n64
template <int KS0, int KSN>
__device__ __forceinline__ void compute_group(
    const uint32_t aRowByte[4], uint32_t bRowByte, const uint32_t boff[4],
    int cb, int rq, float (&acc)[4][8][4]) {
    #pragma unroll
    for (int kk = 0; kk < KSN; ++kk) {
        const int ks = KS0 + kk;
        uint32_t cc = (uint32_t)(ks * 2 + cb);
        uint32_t aoff = ((cc < 32u) ? (cc ^ (uint32_t)rq) : cc) * 16u;
        uint32_t af[4][4], bf[4][4];
        #pragma unroll
        for (int mt = 0; mt < 4; ++mt)
            ldm_x4(af[mt], aRowByte[mt] + aoff);
        uint32_t bks = bRowByte + (uint32_t)(ks * 16 * B_ROWB);
        #pragma unroll
        for (int p = 0; p < 4; ++p)
            ldm_x4_t(bf[p], bks + boff[p]);
        #pragma unroll
        for (int mt = 0; mt < 4; ++mt)
            #pragma unroll
            for (int nt = 0; nt < 8; ++nt) {
                uint32_t bb[2] = { bf[nt >> 1][(nt & 1) * 2],
                                   bf[nt >> 1][(nt & 1) * 2 + 1] };
                mma16816(acc[mt][nt], af[mt], bb);
            }
    }
}

__global__ __launch_bounds__(256, 1)
void gemm_kernel(const int* __restrict__ x, const float* __restrict__ emb,
                 float* __restrict__ out) {
    extern __shared__ char sm[];
    const uint32_t smem_u = (uint32_t)__cvta_generic_to_shared(sm);
    const uint32_t aU = smem_u + B_TOT;

    const int tid  = threadIdx.x;
    const int lane = tid & 31, wid = tid >> 5;       // 8 warps
    const int wm = wid & 1;                          // m64 half
    const int wn = wid >> 1;                         // 0..3 : n64 slice owner pair
    const int m0 = blockIdx.x * MTILE;
    const uint32_t bSliceU = smem_u + (uint32_t)wn * B_SLICE;

    // ---- prologue: steps 0,1 (chunk0 groups 0,1) in flight ----
    issue_group(bSliceU, wn * 64, 0, wm, lane);
    asm volatile("cp.async.commit_group;" ::: "memory");
    issue_group(bSliceU, wn * 64, 1, wm, lane);
    asm volatile("cp.async.commit_group;" ::: "memory");

    // ---- gather A (swizzled, unpadded rows): 128 rows, 2 threads/row ----
    {
        int r = tid >> 1;
        int token = x[m0 + r];
        const float4* src = (const float4*)(emb + (size_t)token * EMB_DIM);
        char* arow = sm + B_TOT + r * A_ROWB;
        int r7 = r & 7;
        #pragma unroll
        for (int j = (tid & 1); j < 75; j += 2) {    // 75 float4 per row
            float4 v = src[j];
            int c16 = j >> 1;
            int swc = (c16 < 32) ? (c16 ^ r7) : c16;
            char* dp = arow + swc * 16 + (j & 1) * 8;
            ((__half2*)dp)[0] = __floats2half2_rn(v.x, v.y);
            ((__half2*)dp)[1] = __floats2half2_rn(v.z, v.w);
        }
        if ((tid & 1) == 0) {                        // zero k 300..303 (seg 37, hi 8B)
            char* dp = arow + 37 * 16 + 8;
            ((__half2*)dp)[0] = __half2half2(__float2half(0.0f));
            ((__half2*)dp)[1] = __half2half2(__float2half(0.0f));
        }
    }
    __syncthreads();    // A visible to all; B is pair-self-synced from here on

    // ---- lane constants ----
    const int bq = lane >> 3, rq = lane & 7, cb = bq >> 1;
    uint32_t aRowByte[4];
    #pragma unroll
    for (int mt = 0; mt < 4; ++mt)
        aRowByte[mt] = aU + (uint32_t)((wm * 64 + mt * 16 + (bq & 1) * 8 + rq) * A_ROWB);
    const uint32_t bRowByte = bSliceU + (uint32_t)(((bq & 1) * 8 + rq) * B_ROWB);
    uint32_t boff[4];
    #pragma unroll
    for (int p = 0; p < 4; ++p)
        boff[p] = (uint32_t)(((p * 2 + cb) ^ rq) * 16);
    const int barId = wn + 1;

    float acc[4][8][4];
    #pragma unroll
    for (int mt = 0; mt < 4; ++mt)
        #pragma unroll
        for (int nt = 0; nt < 8; ++nt)
            #pragma unroll
            for (int q = 0; q < 4; ++q) acc[mt][nt][q] = 0.0f;

    int s = 0;
    #pragma unroll 1
    for (int c = 0; c < NCHUNKS; ++c) {
        #pragma unroll 1
        for (int g = 0; g < NGRP; ++g, ++s) {
            // data for step s = commit #(s+1); keep <=1 pending
            asm volatile("cp.async.wait_group 1;" ::: "memory");
            asm volatile("bar.sync %0, 64;" :: "r"(barId) : "memory");

            if (g == 0)      compute_group<0, 7>(aRowByte, bRowByte, boff, cb, rq, acc);
            else if (g == 1) compute_group<7, 6>(aRowByte, bRowByte, boff, cb, rq, acc);
            else             compute_group<13, 6>(aRowByte, bRowByte, boff, cb, rq, acc);

            // refill region consumed at step s-1 (== region of step s+2)
            int s2 = s + 2;
            if (s2 < NSTEPS) {
                int c2 = s2 / NGRP, g2 = s2 - c2 * NGRP;
                issue_group(bSliceU, c2 * NCHUNK + wn * 64, g2, wm, lane);
            }
            asm volatile("cp.async.commit_group;" ::: "memory");
        }

        // ---- epilogue for chunk c (no barrier; overlaps other pairs) ----
        int n0 = c * NCHUNK;
        #pragma unroll
        for (int nt = 0; nt < 8; ++nt) {
            int col = n0 + wn * 64 + nt * 8 + (lane & 3) * 2;
            float2 cbia = *(const float2*)(g_bs + col);
            #pragma unroll
            for (int mt = 0; mt < 4; ++mt) {
                int row = m0 + wm * 64 + mt * 16 + (lane >> 2);
                float2 v0 = { fmaf(acc[mt][nt][0], SCALE, cbia.x),
                              fmaf(acc[mt][nt][1], SCALE, cbia.y) };
                float2 v1 = { fmaf(acc[mt][nt][2], SCALE, cbia.x),
                              fmaf(acc[mt][nt][3], SCALE, cbia.y) };
                *(float2*)(out + (size_t)row * NTOT + col)       = v0;
                *(float2*)(out + (size_t)(row + 8) * NTOT + col) = v1;
                acc[mt][nt][0] = 0.0f; acc[mt][nt][1] = 0.0f;
                acc[mt][nt][2] = 0.0f; acc[mt][nt][3] = 0.0f;
            }
        }
    }
}

extern "C" void kernel_launch(void* const* d_in, const int* in_sizes, int n_in,
                              void* d_out, int out_size) {
    const int*   x    = (const int*)  d_in[0];
    const float* emb  = (const float*)d_in[1];
    const float* W    = (const float*)d_in[2];
    const float* bias = (const float*)d_in[3];
    float*       out  = (float*)      d_out;

    cudaFuncSetAttribute(gemm_kernel, cudaFuncAttributeMaxDynamicSharedMemorySize,
                         SMEM_BYTES);

    prep<<<(KP * NTOT + 255) / 256, 256>>>(W, bias);
    gemm_kernel<<<MTOT / MTILE, 256, SMEM_BYTES>>>(x, emb, out);
}

// round 14
// speedup vs baseline: 1.4321x; 1.0386x over previous
#include <cuda_runtime.h>
#include <cuda_fp16.h>
#include <cstdint>

#define EMB_DIM 300
#define KP      304
#define NTOT    2048
#define MTOT    32768
#define MTILE   128
#define NCHUNK  256
#define NCHUNKS (NTOT / NCHUNK)      // 8
#define NGRP    3                    // K-groups per chunk (7/6/6 ksteps)
#define NSTEPS  (NCHUNKS * NGRP)     // 24 pipeline steps
#define A_ROWB  608                  // 304 halves, unpadded, swizzled
#define B_ROWB  128                  // 64 halves per slice row, swizzled
#define B_SLICE (300 * B_ROWB)       // 38400 (rows 300-303 never loaded)
#define B_TOT   (4 * B_SLICE)        // 153600
#define A_BYTES (MTILE * A_ROWB)     // 77824
#define SMEM_BYTES (B_TOT + A_BYTES) // 231424 <= 232448
#define SCALE 45.254833995939045f

__device__ __half g_Wh[KP * NTOT];   // fp16 W, K zero-padded rows
__device__ float  g_bs[NTOT];        // bias * scale

__global__ void prep(const float* __restrict__ W, const float* __restrict__ b) {
    int i = blockIdx.x * blockDim.x + threadIdx.x;
    if (i < KP * NTOT) {
        int k = i / NTOT, n = i % NTOT;
        g_Wh[i] = __float2half_rn((k < EMB_DIM) ? W[k * NTOT + n] : 0.0f);
    }
    if (i < NTOT) g_bs[i] = b[i] * SCALE;
}

__device__ __forceinline__ void ldm_x4(uint32_t* r, uint32_t a) {
    asm volatile("ldmatrix.sync.aligned.m8n8.x4.shared.b16 {%0,%1,%2,%3}, [%4];"
                 : "=r"(r[0]), "=r"(r[1]), "=r"(r[2]), "=r"(r[3]) : "r"(a));
}
__device__ __forceinline__ void ldm_x4_t(uint32_t* r, uint32_t a) {
    asm volatile("ldmatrix.sync.aligned.m8n8.x4.trans.shared.b16 {%0,%1,%2,%3}, [%4];"
                 : "=r"(r[0]), "=r"(r[1]), "=r"(r[2]), "=r"(r[3]) : "r"(a));
}
__device__ __forceinline__ void mma16816(float* d, const uint32_t* a, const uint32_t* b) {
    asm volatile("mma.sync.aligned.m16n8k16.row.col.f32.f16.f16.f32 "
                 "{%0,%1,%2,%3}, {%4,%5,%6,%7}, {%8,%9}, {%0,%1,%2,%3};"
                 : "+f"(d[0]), "+f"(d[1]), "+f"(d[2]), "+f"(d[3])
                 : "r"(a[0]), "r"(a[1]), "r"(a[2]), "r"(a[3]),
                   "r"(b[0]), "r"(b[1]));
}

// cp.async one K-group of a slice. Row windows: g0 [0,112) g1 [112,208)
// g2 [208,300). The 4 warps of the slice group (wm 0..3) split each window.
__device__ __forceinline__ void issue_group(uint32_t bSliceU, int n0, int g,
                                            int wm, int lane) {
    int start = (g == 0) ? 0 : (g == 1 ? 112 : 208);
    int cnt   = (g == 0) ? 28 : (g == 1 ? 24 : 23);   // per-warp rows
    start += wm * cnt;
    int seg = lane & 7;
    int r0  = start + (lane >> 3);
    int iters = (cnt + 3) >> 2;
    for (int it = 0; it < iters; ++it) {
        int row = r0 + it * 4;
        if (row < start + cnt) {
            uint32_t dst = bSliceU + (uint32_t)row * B_ROWB
                         + (uint32_t)((seg ^ (row & 7)) * 16);
            size_t gsrc = __cvta_generic_to_global(
                g_Wh + (size_t)row * NTOT + n0 + seg * 8);
            asm volatile("cp.async.cg.shared.global [%0], [%1], 16;"
                         :: "r"(dst), "l"(gsrc));
        }
    }
}

// fully-unrolled K-group compute: ksteps [KS0, KS0+KSN), warp tile m32 x n64
template <int KS0, int KSN>
__device__ __forceinline__ void compute_group(
    const uint32_t aRowByte[2], uint32_t bRowByte, const uint32_t boff[4],
    int cb, int rq, float (&acc)[2][8][4]) {
    #pragma unroll
    for (int kk = 0; kk < KSN; ++kk) {
        const int ks = KS0 + kk;
        uint32_t cc = (uint32_t)(ks * 2 + cb);
        uint32_t aoff = ((cc < 32u) ? (cc ^ (uint32_t)rq) : cc) * 16u;
        uint32_t af[2][4], bf[4][4];
        #pragma unroll
        for (int mt = 0; mt < 2; ++mt)
            ldm_x4(af[mt], aRowByte[mt] + aoff);
        uint32_t bks = bRowByte + (uint32_t)(ks * 16 * B_ROWB);
        #pragma unroll
        for (int p = 0; p < 4; ++p)
            ldm_x4_t(bf[p], bks + boff[p]);
        #pragma unroll
        for (int mt = 0; mt < 2; ++mt)
            #pragma unroll
            for (int nt = 0; nt < 8; ++nt) {
                uint32_t bb[2] = { bf[nt >> 1][(nt & 1) * 2],
                                   bf[nt >> 1][(nt & 1) * 2 + 1] };
                mma16816(acc[mt][nt], af[mt], bb);
            }
    }
}

__global__ __launch_bounds__(512, 1)
void gemm_kernel(const int* __restrict__ x, const float* __restrict__ emb,
                 float* __restrict__ out) {
    extern __shared__ char sm[];
    const uint32_t smem_u = (uint32_t)__cvta_generic_to_shared(sm);
    const uint32_t aU = smem_u + B_TOT;

    const int tid  = threadIdx.x;
    const int lane = tid & 31, wid = tid >> 5;       // 16 warps
    const int wm = wid & 3;                          // 0..3 : m32 band
    const int wn = wid >> 2;                         // 0..3 : n64 slice group
    const int m0 = blockIdx.x * MTILE;
    const uint32_t bSliceU = smem_u + (uint32_t)wn * B_SLICE;

    // ---- prologue: steps 0,1 (chunk0 groups 0,1) in flight ----
    issue_group(bSliceU, wn * 64, 0, wm, lane);
    asm volatile("cp.async.commit_group;" ::: "memory");
    issue_group(bSliceU, wn * 64, 1, wm, lane);
    asm volatile("cp.async.commit_group;" ::: "memory");

    // ---- gather A (swizzled, unpadded rows): 128 rows, 4 threads/row ----
    {
        int r = tid >> 2;
        int token = x[m0 + r];
        const float4* src = (const float4*)(emb + (size_t)token * EMB_DIM);
        char* arow = sm + B_TOT + r * A_ROWB;
        int r7 = r & 7;
        #pragma unroll
        for (int j = (tid & 3); j < 75; j += 4) {    // 75 float4 per row
            float4 v = src[j];
            int c16 = j >> 1;
            int swc = (c16 < 32) ? (c16 ^ r7) : c16;
            char* dp = arow + swc * 16 + (j & 1) * 8;
            ((__half2*)dp)[0] = __floats2half2_rn(v.x, v.y);
            ((__half2*)dp)[1] = __floats2half2_rn(v.z, v.w);
        }
        if ((tid & 3) == 0) {                        // zero k 300..303 (seg 37, hi 8B)
            char* dp = arow + 37 * 16 + 8;
            ((__half2*)dp)[0] = __half2half2(__float2half(0.0f));
            ((__half2*)dp)[1] = __half2half2(__float2half(0.0f));
        }
    }
    __syncthreads();    // A visible to all; B is group-self-synced from here on

    // ---- lane constants ----
    const int bq = lane >> 3, rq = lane & 7, cb = bq >> 1;
    uint32_t aRowByte[2];
    #pragma unroll
    for (int mt = 0; mt < 2; ++mt)
        aRowByte[mt] = aU + (uint32_t)((wm * 32 + mt * 16 + (bq & 1) * 8 + rq) * A_ROWB);
    const uint32_t bRowByte = bSliceU + (uint32_t)(((bq & 1) * 8 + rq) * B_ROWB);
    uint32_t boff[4];
    #pragma unroll
    for (int p = 0; p < 4; ++p)
        boff[p] = (uint32_t)(((p * 2 + cb) ^ rq) * 16);
    const int barId = wn + 1;

    float acc[2][8][4];
    #pragma unroll
    for (int mt = 0; mt < 2; ++mt)
        #pragma unroll
        for (int nt = 0; nt < 8; ++nt)
            #pragma unroll
            for (int q = 0; q < 4; ++q) acc[mt][nt][q] = 0.0f;

    int s = 0;
    #pragma unroll 1
    for (int c = 0; c < NCHUNKS; ++c) {
        #pragma unroll 1
        for (int g = 0; g < NGRP; ++g, ++s) {
            // data for step s = commit #(s+1); keep <=1 pending
            asm volatile("cp.async.wait_group 1;" ::: "memory");
            asm volatile("bar.sync %0, 128;" :: "r"(barId) : "memory");

            if (g == 0)      compute_group<0, 7>(aRowByte, bRowByte, boff, cb, rq, acc);
            else if (g == 1) compute_group<7, 6>(aRowByte, bRowByte, boff, cb, rq, acc);
            else             compute_group<13, 6>(aRowByte, bRowByte, boff, cb, rq, acc);

            // refill region consumed at step s-1 (== region of step s+2)
            int s2 = s + 2;
            if (s2 < NSTEPS) {
                int c2 = s2 / NGRP, g2 = s2 - c2 * NGRP;
                issue_group(bSliceU, c2 * NCHUNK + wn * 64, g2, wm, lane);
            }
            asm volatile("cp.async.commit_group;" ::: "memory");
        }

        // ---- epilogue for chunk c (no barrier; overlaps other groups) ----
        int n0 = c * NCHUNK;
        #pragma unroll
        for (int nt = 0; nt < 8; ++nt) {
            int col = n0 + wn * 64 + nt * 8 + (lane & 3) * 2;
            float2 cbia = *(const float2*)(g_bs + col);
            #pragma unroll
            for (int mt = 0; mt < 2; ++mt) {
                int row = m0 + wm * 32 + mt * 16 + (lane >> 2);
                float2 v0 = { fmaf(acc[mt][nt][0], SCALE, cbia.x),
                              fmaf(acc[mt][nt][1], SCALE, cbia.y) };
                float2 v1 = { fmaf(acc[mt][nt][2], SCALE, cbia.x),
                              fmaf(acc[mt][nt][3], SCALE, cbia.y) };
                *(float2*)(out + (size_t)row * NTOT + col)       = v0;
                *(float2*)(out + (size_t)(row + 8) * NTOT + col) = v1;
                acc[mt][nt][0] = 0.0f; acc[mt][nt][1] = 0.0f;
                acc[mt][nt][2] = 0.0f; acc[mt][nt][3] = 0.0f;
            }
        }
    }
}

extern "C" void kernel_launch(void* const* d_in, const int* in_sizes, int n_in,
                              void* d_out, int out_size) {
    const int*   x    = (const int*)  d_in[0];
    const float* emb  = (const float*)d_in[1];
    const float* W    = (const float*)d_in[2];
    const float* bias = (const float*)d_in[3];
    float*       out  = (float*)      d_out;

    cudaFuncSetAttribute(gemm_kernel, cudaFuncAttributeMaxDynamicSharedMemorySize,
                         SMEM_BYTES);

    prep<<<(KP * NTOT + 255) / 256, 256>>>(W, bias);
    gemm_kernel<<<MTOT / MTILE, 512, SMEM_BYTES>>>(x, emb, out);
}